// round 1
// baseline (speedup 1.0000x reference)
#include <cuda_runtime.h>

#define D      512
#define BATCH  256
#define TOPK   2
#define NEXP   16
#define NPAIR  (BATCH * TOPK)
#define XS_STRIDE 20   // floats per kk row in smem (16 data + 4 pad, keeps 16B align, spreads banks)

// ---------------- scratch (device globals; no allocations allowed) ----------------
__device__ float g_iv[NPAIR * D];
__device__ float g_ov[NPAIR * D];
__device__ float g_dv[NPAIR * D];
__device__ float g_bv[NPAIR * D];
__device__ int   g_list_w[NPAIR];
__device__ int   g_list_b[NPAIR];
__device__ int   g_off_w[NEXP + 1];
__device__ int   g_off_b[NEXP + 1];

// ---------------- kernel 0: counting sort of (b,k) pairs by expert ----------------
__global__ void sort_kernel(const int* __restrict__ widx, const int* __restrict__ bidx) {
    __shared__ int cw[NEXP], cb[NEXP], offw[NEXP + 1], offb[NEXP + 1], pw[NEXP], pb[NEXP];
    int t = threadIdx.x;                       // 512 threads, t == pair id
    if (t < NEXP) { cw[t] = 0; cb[t] = 0; }
    __syncthreads();
    int ew = widx[t];
    int eb = bidx[t];
    atomicAdd(&cw[ew], 1);
    atomicAdd(&cb[eb], 1);
    __syncthreads();
    if (t == 0) {
        int s = 0;
        for (int e = 0; e < NEXP; e++) { offw[e] = s; s += cw[e]; }
        offw[NEXP] = s;
        s = 0;
        for (int e = 0; e < NEXP; e++) { offb[e] = s; s += cb[e]; }
        offb[NEXP] = s;
    }
    __syncthreads();
    if (t < NEXP) {
        pw[t] = offw[t]; pb[t] = offb[t];
        g_off_w[t] = offw[t]; g_off_b[t] = offb[t];
    }
    if (t == 0) { g_off_w[NEXP] = NPAIR; g_off_b[NEXP] = NPAIR; }
    __syncthreads();
    int posw = atomicAdd(&pw[ew], 1);
    g_list_w[posw] = t;
    int posb = atomicAdd(&pb[eb], 1);
    g_list_b[posb] = t;
}

// ---------------- kernel 1: grouped GEMM over experts x 4 banks ----------------
// grid = (4 col-tiles of 128, 16 experts, 4 banks), block = 256 threads.
// Thread layout: col = tid&127 within the 128-col tile, rg = tid>>7 picks rows
// [rg*8, rg*8+8) of the current 16-row chunk. x chunk lives transposed in smem
// (xs[kk][m], stride 20) so the inner loop is 1 LDG + 2 LDS.128 + 8 FFMA per kk.
__global__ __launch_bounds__(256, 2) void gemm_kernel(
    const float* __restrict__ x,
    const float* __restrict__ iw, const float* __restrict__ ow,
    const float* __restrict__ dw, const float* __restrict__ bb) {

    __shared__ __align__(16) float xs[D * XS_STRIDE];

    int bank = blockIdx.z;
    int e    = blockIdx.y;
    int col0 = blockIdx.x * 128;

    const int* list = (bank < 3) ? g_list_w : g_list_b;
    const int* off  = (bank < 3) ? g_off_w  : g_off_b;
    const float* W  = ((bank == 0) ? iw : (bank == 1) ? ow : (bank == 2) ? dw : bb)
                      + (size_t)e * D * D;
    float* out = (bank == 0) ? g_iv : (bank == 1) ? g_ov : (bank == 2) ? g_dv : g_bv;

    int m0 = off[e];
    int M  = off[e + 1] - m0;

    int tid = threadIdx.x;
    int col = col0 + (tid & 127);
    int rg  = tid >> 7;                     // 0 or 1
    const float* Wc = W + col;

    for (int chunk = 0; chunk < M; chunk += 16) {
        // cooperative fill of transposed x chunk (zero-padded rows)
        for (int idx = tid; idx < 16 * D; idx += 256) {
            int m  = idx >> 9;
            int kk = idx & (D - 1);
            float val = 0.0f;
            int mm = chunk + m;
            if (mm < M) {
                int pair = list[m0 + mm];
                val = x[(pair >> 1) * D + kk];
            }
            xs[kk * XS_STRIDE + m] = val;
        }
        __syncthreads();

        float acc[8];
#pragma unroll
        for (int r = 0; r < 8; r++) acc[r] = 0.0f;

#pragma unroll 8
        for (int kk = 0; kk < D; kk++) {
            float w = Wc[kk * D];
            float4 xa = *(const float4*)&xs[kk * XS_STRIDE + rg * 8];
            float4 xb = *(const float4*)&xs[kk * XS_STRIDE + rg * 8 + 4];
            acc[0] = fmaf(xa.x, w, acc[0]);
            acc[1] = fmaf(xa.y, w, acc[1]);
            acc[2] = fmaf(xa.z, w, acc[2]);
            acc[3] = fmaf(xa.w, w, acc[3]);
            acc[4] = fmaf(xb.x, w, acc[4]);
            acc[5] = fmaf(xb.y, w, acc[5]);
            acc[6] = fmaf(xb.z, w, acc[6]);
            acc[7] = fmaf(xb.w, w, acc[7]);
        }

#pragma unroll
        for (int r = 0; r < 8; r++) {
            int mm = chunk + rg * 8 + r;
            if (mm < M) out[(size_t)list[m0 + mm] * D + col] = acc[r];
        }
        __syncthreads();   // xs reads done before next fill
    }
}

// ---------------- kernel 2: rank-2 mix + analytic LayerNorm + bmix ----------------
// Wmix[b,i,o] = p_i*u_o + q_i*v_o + delta_{io}*g_i   with
//   p_i = wp0*iv0[i], q_i = wp1*iv1[i], u = ov0, v = ov1, g_i = wp0*dv0[i]+wp1*dv1[i]
// mean/var per row are closed-form from Su,Sv,Suu,Svv,Suv (per-b scalars) => one pass.
// grid = (4 row-tiles of 128, B), block = 128 threads (each owns 4 output cols).
__global__ __launch_bounds__(128) void mix_ln_kernel(
    const float* __restrict__ wp, const float* __restrict__ bp,
    float* __restrict__ outp) {

    int b  = blockIdx.y;
    int r0 = blockIdx.x * 128;
    int t  = threadIdx.x;

    __shared__ float u[D], v[D];
    __shared__ float sp[128], sq[128], sg[128], sm[128], sr[128];
    __shared__ float red[4][5];

    const float* u_g = g_ov + (size_t)(2 * b) * D;
    const float* v_g = g_ov + (size_t)(2 * b + 1) * D;
    float4 u4 = ((const float4*)u_g)[t];
    float4 v4 = ((const float4*)v_g)[t];
    ((float4*)u)[t] = u4;
    ((float4*)v)[t] = v4;

    // per-b scalar sums
    float lu  = u4.x + u4.y + u4.z + u4.w;
    float lv  = v4.x + v4.y + v4.z + v4.w;
    float luu = u4.x * u4.x + u4.y * u4.y + u4.z * u4.z + u4.w * u4.w;
    float lvv = v4.x * v4.x + v4.y * v4.y + v4.z * v4.z + v4.w * v4.w;
    float luv = u4.x * v4.x + u4.y * v4.y + u4.z * v4.z + u4.w * v4.w;
#pragma unroll
    for (int s = 16; s > 0; s >>= 1) {
        lu  += __shfl_xor_sync(0xffffffffu, lu, s);
        lv  += __shfl_xor_sync(0xffffffffu, lv, s);
        luu += __shfl_xor_sync(0xffffffffu, luu, s);
        lvv += __shfl_xor_sync(0xffffffffu, lvv, s);
        luv += __shfl_xor_sync(0xffffffffu, luv, s);
    }
    int lane = t & 31, wrp = t >> 5;
    if (lane == 0) {
        red[wrp][0] = lu; red[wrp][1] = lv; red[wrp][2] = luu;
        red[wrp][3] = lvv; red[wrp][4] = luv;
    }
    __syncthreads();
    float Su  = red[0][0] + red[1][0] + red[2][0] + red[3][0];
    float Sv  = red[0][1] + red[1][1] + red[2][1] + red[3][1];
    float Suu = red[0][2] + red[1][2] + red[2][2] + red[3][2];
    float Svv = red[0][3] + red[1][3] + red[2][3] + red[3][3];
    float Suv = red[0][4] + red[1][4] + red[2][4] + red[3][4];

    // per-row scalars for the 128 rows this block owns (one row per thread)
    {
        int i = r0 + t;
        float wp0 = wp[2 * b], wp1 = wp[2 * b + 1];
        float p = wp0 * g_iv[(size_t)(2 * b) * D + i];
        float q = wp1 * g_iv[(size_t)(2 * b + 1) * D + i];
        float g = wp0 * g_dv[(size_t)(2 * b) * D + i]
                + wp1 * g_dv[(size_t)(2 * b + 1) * D + i];
        const float invD = 1.0f / (float)D;
        float mean = (p * Su + q * Sv + g) * invD;
        float ex2  = (p * p * Suu + 2.0f * p * q * Suv + q * q * Svv
                      + 2.0f * g * (p * u[i] + q * v[i]) + g * g) * invD;
        float var  = ex2 - mean * mean;
        sp[t] = p; sq[t] = q; sg[t] = g; sm[t] = mean;
        sr[t] = rsqrtf(var + 1e-5f);
    }
    __syncthreads();

    float* orow = outp + ((size_t)b * D + r0) * D + t * 4;
#pragma unroll 4
    for (int r = 0; r < 128; r++) {
        float p = sp[r], q = sq[r], mean = sm[r], rstd = sr[r];
        int i = r0 + r;
        float wv[4];
        wv[0] = p * u4.x + q * v4.x;
        wv[1] = p * u4.y + q * v4.y;
        wv[2] = p * u4.z + q * v4.z;
        wv[3] = p * u4.w + q * v4.w;
        int base = t << 2;
#pragma unroll
        for (int j = 0; j < 4; j++)
            wv[j] += (i == base + j) ? sg[r] : 0.0f;
        float4 o;
        o.x = (wv[0] - mean) * rstd;
        o.y = (wv[1] - mean) * rstd;
        o.z = (wv[2] - mean) * rstd;
        o.w = (wv[3] - mean) * rstd;
        *(float4*)(orow + (size_t)r * D) = o;
    }

    // bmix (only row-tile 0 blocks): bmix[b,:] = bp0*bv0 + bp1*bv1
    if (blockIdx.x == 0) {
        float bp0 = bp[2 * b], bp1 = bp[2 * b + 1];
        float4 b0 = ((const float4*)(g_bv + (size_t)(2 * b) * D))[t];
        float4 b1 = ((const float4*)(g_bv + (size_t)(2 * b + 1) * D))[t];
        float4 o;
        o.x = bp0 * b0.x + bp1 * b1.x;
        o.y = bp0 * b0.y + bp1 * b1.y;
        o.z = bp0 * b0.z + bp1 * b1.z;
        o.w = bp0 * b0.w + bp1 * b1.w;
        ((float4*)(outp + (size_t)BATCH * D * D + (size_t)b * D))[t] = o;
    }
}

// ---------------- launch ----------------
extern "C" void kernel_launch(void* const* d_in, const int* in_sizes, int n_in,
                              void* d_out, int out_size) {
    const float* x    = (const float*)d_in[0];
    const float* wp   = (const float*)d_in[1];
    const float* bpr  = (const float*)d_in[2];
    const float* iw   = (const float*)d_in[3];
    const float* ow   = (const float*)d_in[4];
    const float* dw   = (const float*)d_in[5];
    const float* bb   = (const float*)d_in[6];
    const int*   widx = (const int*)d_in[7];
    const int*   bidx = (const int*)d_in[8];
    float* outp = (float*)d_out;

    sort_kernel<<<1, NPAIR>>>(widx, bidx);
    gemm_kernel<<<dim3(4, NEXP, 4), 256>>>(x, iw, ow, dw, bb);
    mix_ln_kernel<<<dim3(4, BATCH), 128>>>(wp, bpr, outp);
}

// round 2
// speedup vs baseline: 1.3067x; 1.3067x over previous
#include <cuda_runtime.h>

#define D      512
#define BATCH  256
#define TOPK   2
#define NEXP   16
#define NPAIR  (BATCH * TOPK)
#define MAXCH  64          // >= worst-case sum ceil(M_e/16) = 48
#define XS_STRIDE 20       // 16 data + 4 pad floats; keeps 16B alignment, spreads banks

// ---------------- scratch ----------------
__device__ float g_iv[NPAIR * D];
__device__ float g_ov[NPAIR * D];
__device__ float g_dv[NPAIR * D];
__device__ float g_bv[NPAIR * D];
__device__ int   g_list_w[NPAIR];
__device__ int   g_list_b[NPAIR];
__device__ int   g_chunks_w[MAXCH];   // packed: start | e<<16 | rows<<24
__device__ int   g_chunks_b[MAXCH];
__device__ int   g_nch_w, g_nch_b;

// ---------------- kernel 0: counting sort + chunk work-list ----------------
__global__ void sort_kernel(const int* __restrict__ widx, const int* __restrict__ bidx) {
    __shared__ int cw[NEXP], cb[NEXP], offw[NEXP + 1], offb[NEXP + 1], pw[NEXP], pb[NEXP];
    int t = threadIdx.x;                       // 512 threads == pair id
    if (t < NEXP) { cw[t] = 0; cb[t] = 0; }
    __syncthreads();
    int ew = widx[t];
    int eb = bidx[t];
    atomicAdd(&cw[ew], 1);
    atomicAdd(&cb[eb], 1);
    __syncthreads();
    if (t == 0) {
        int s = 0;
        for (int e = 0; e < NEXP; e++) { offw[e] = s; s += cw[e]; }
        offw[NEXP] = s;
        int n = 0;
        for (int e = 0; e < NEXP; e++)
            for (int c = offw[e]; c < offw[e + 1]; c += 16) {
                int rows = min(16, offw[e + 1] - c);
                g_chunks_w[n++] = c | (e << 16) | (rows << 24);
            }
        g_nch_w = n;
    }
    if (t == 32) {
        int s = 0;
        for (int e = 0; e < NEXP; e++) { offb[e] = s; s += cb[e]; }
        offb[NEXP] = s;
        int n = 0;
        for (int e = 0; e < NEXP; e++)
            for (int c = offb[e]; c < offb[e + 1]; c += 16) {
                int rows = min(16, offb[e + 1] - c);
                g_chunks_b[n++] = c | (e << 16) | (rows << 24);
            }
        g_nch_b = n;
    }
    __syncthreads();
    if (t < NEXP) { pw[t] = offw[t]; pb[t] = offb[t]; }
    __syncthreads();
    int posw = atomicAdd(&pw[ew], 1);
    g_list_w[posw] = t;
    int posb = atomicAdd(&pb[eb], 1);
    g_list_b[posb] = t;
}

// ---------------- kernel 1: balanced grouped GEMM ----------------
// grid = (4 col-tiles of 128, MAXCH chunk slots, 4 banks), block = 128 threads.
// One 16-row chunk per block; thread owns 1 column and 16 row-accumulators.
// Inner loop per kk: 1 LDG (W, coalesced) + 4 LDS.128 (broadcast) + 16 FFMA.
__global__ __launch_bounds__(128) void gemm_kernel(
    const float* __restrict__ x,
    const float* __restrict__ iw, const float* __restrict__ ow,
    const float* __restrict__ dw, const float* __restrict__ bb) {

    int bank = blockIdx.z;
    bool isW = bank < 3;
    int nch = isW ? g_nch_w : g_nch_b;
    if ((int)blockIdx.y >= nch) return;

    __shared__ __align__(16) float xs[D * XS_STRIDE];   // 40KB

    int packed = (isW ? g_chunks_w : g_chunks_b)[blockIdx.y];
    int s    = packed & 0xFFFF;
    int e    = (packed >> 16) & 0xFF;
    int rows = (packed >> 24) & 0xFF;

    const int* list = isW ? g_list_w : g_list_b;
    const float* W  = ((bank == 0) ? iw : (bank == 1) ? ow : (bank == 2) ? dw : bb)
                      + (size_t)e * D * D;
    float* out = (bank == 0) ? g_iv : (bank == 1) ? g_ov : (bank == 2) ? g_dv : g_bv;

    int t    = threadIdx.x;
    int col  = blockIdx.x * 128 + t;

    // fill transposed x chunk (coalesced LDG; STS stride-20 => mild 4-way conflict)
    for (int idx = t; idx < 16 * D; idx += 128) {
        int m  = idx >> 9;
        int kk = idx & (D - 1);
        float val = 0.0f;
        if (m < rows) val = x[(list[s + m] >> 1) * D + kk];
        xs[kk * XS_STRIDE + m] = val;
    }
    __syncthreads();

    float acc[16];
#pragma unroll
    for (int r = 0; r < 16; r++) acc[r] = 0.0f;

    const float* Wc = W + col;
#pragma unroll 8
    for (int kk = 0; kk < D; kk++) {
        float w = Wc[kk * D];
        const float* row = &xs[kk * XS_STRIDE];
        float4 a0 = *(const float4*)(row + 0);
        float4 a1 = *(const float4*)(row + 4);
        float4 a2 = *(const float4*)(row + 8);
        float4 a3 = *(const float4*)(row + 12);
        acc[0]  = fmaf(a0.x, w, acc[0]);
        acc[1]  = fmaf(a0.y, w, acc[1]);
        acc[2]  = fmaf(a0.z, w, acc[2]);
        acc[3]  = fmaf(a0.w, w, acc[3]);
        acc[4]  = fmaf(a1.x, w, acc[4]);
        acc[5]  = fmaf(a1.y, w, acc[5]);
        acc[6]  = fmaf(a1.z, w, acc[6]);
        acc[7]  = fmaf(a1.w, w, acc[7]);
        acc[8]  = fmaf(a2.x, w, acc[8]);
        acc[9]  = fmaf(a2.y, w, acc[9]);
        acc[10] = fmaf(a2.z, w, acc[10]);
        acc[11] = fmaf(a2.w, w, acc[11]);
        acc[12] = fmaf(a3.x, w, acc[12]);
        acc[13] = fmaf(a3.y, w, acc[13]);
        acc[14] = fmaf(a3.z, w, acc[14]);
        acc[15] = fmaf(a3.w, w, acc[15]);
    }

#pragma unroll
    for (int r = 0; r < 16; r++)
        if (r < rows) out[(size_t)list[s + r] * D + col] = acc[r];
}

// ---------------- kernel 2: rank-2 mix + analytic LayerNorm + bmix ----------------
// Wmix[b,i,o] = p_i*u_o + q_i*v_o + delta_{io}*g_i. Row mean/var closed-form from
// Su,Sv,Suu,Svv,Suv. Per-row params folded to (pr,qr,c,gr) = (p*rstd, q*rstd,
// -mean*rstd, g*rstd) so inner body = 1 LDS.128 + 8 FFMA + STG.128.
// Diagonal hits only warp blockIdx.x (rows 4t-r0 in [0,128) <=> t>>5 == bx).
__global__ __launch_bounds__(128) void mix_ln_kernel(
    const float* __restrict__ wp, const float* __restrict__ bp,
    float* __restrict__ outp) {

    int b  = blockIdx.y;
    int r0 = blockIdx.x * 128;
    int t  = threadIdx.x;

    __shared__ float u[D], v[D];
    __shared__ __align__(16) float4 sparams[128];   // {pr, qr, c, gr}
    __shared__ float red[4][5];

    const float* u_g = g_ov + (size_t)(2 * b) * D;
    const float* v_g = g_ov + (size_t)(2 * b + 1) * D;
    float4 u4 = ((const float4*)u_g)[t];
    float4 v4 = ((const float4*)v_g)[t];
    ((float4*)u)[t] = u4;
    ((float4*)v)[t] = v4;

    float lu  = u4.x + u4.y + u4.z + u4.w;
    float lv  = v4.x + v4.y + v4.z + v4.w;
    float luu = u4.x * u4.x + u4.y * u4.y + u4.z * u4.z + u4.w * u4.w;
    float lvv = v4.x * v4.x + v4.y * v4.y + v4.z * v4.z + v4.w * v4.w;
    float luv = u4.x * v4.x + u4.y * v4.y + u4.z * v4.z + u4.w * v4.w;
#pragma unroll
    for (int sft = 16; sft > 0; sft >>= 1) {
        lu  += __shfl_xor_sync(0xffffffffu, lu, sft);
        lv  += __shfl_xor_sync(0xffffffffu, lv, sft);
        luu += __shfl_xor_sync(0xffffffffu, luu, sft);
        lvv += __shfl_xor_sync(0xffffffffu, lvv, sft);
        luv += __shfl_xor_sync(0xffffffffu, luv, sft);
    }
    int lane = t & 31, wrp = t >> 5;
    if (lane == 0) {
        red[wrp][0] = lu; red[wrp][1] = lv; red[wrp][2] = luu;
        red[wrp][3] = lvv; red[wrp][4] = luv;
    }
    __syncthreads();
    float Su  = red[0][0] + red[1][0] + red[2][0] + red[3][0];
    float Sv  = red[0][1] + red[1][1] + red[2][1] + red[3][1];
    float Suu = red[0][2] + red[1][2] + red[2][2] + red[3][2];
    float Svv = red[0][3] + red[1][3] + red[2][3] + red[3][3];
    float Suv = red[0][4] + red[1][4] + red[2][4] + red[3][4];

    {
        int i = r0 + t;
        float wp0 = wp[2 * b], wp1 = wp[2 * b + 1];
        float p = wp0 * g_iv[(size_t)(2 * b) * D + i];
        float q = wp1 * g_iv[(size_t)(2 * b + 1) * D + i];
        float g = wp0 * g_dv[(size_t)(2 * b) * D + i]
                + wp1 * g_dv[(size_t)(2 * b + 1) * D + i];
        const float invD = 1.0f / (float)D;
        float mean = (p * Su + q * Sv + g) * invD;
        float ex2  = (p * p * Suu + 2.0f * p * q * Suv + q * q * Svv
                      + 2.0f * g * (p * u[i] + q * v[i]) + g * g) * invD;
        float var  = ex2 - mean * mean;
        float rstd = rsqrtf(var + 1e-5f);
        float4 pr;
        pr.x = p * rstd;
        pr.y = q * rstd;
        pr.z = -mean * rstd;
        pr.w = g * rstd;
        sparams[t] = pr;
    }
    __syncthreads();

    float* orow = outp + ((size_t)b * D + r0) * D + (t << 2);

    if (wrp == blockIdx.x) {
        // this warp owns the diagonal columns of this row tile
        int base = t << 2;
#pragma unroll 4
        for (int r = 0; r < 128; r++) {
            float4 P = sparams[r];
            float4 o;
            o.x = fmaf(P.y, v4.x, fmaf(P.x, u4.x, P.z));
            o.y = fmaf(P.y, v4.y, fmaf(P.x, u4.y, P.z));
            o.z = fmaf(P.y, v4.z, fmaf(P.x, u4.z, P.z));
            o.w = fmaf(P.y, v4.w, fmaf(P.x, u4.w, P.z));
            int dj = (r0 + r) - base;
            if (dj == 0) o.x += P.w;
            if (dj == 1) o.y += P.w;
            if (dj == 2) o.z += P.w;
            if (dj == 3) o.w += P.w;
            *(float4*)(orow + (size_t)r * D) = o;
        }
    } else {
        // diag never lands in these columns: clean streaming loop
#pragma unroll 4
        for (int r = 0; r < 128; r++) {
            float4 P = sparams[r];
            float4 o;
            o.x = fmaf(P.y, v4.x, fmaf(P.x, u4.x, P.z));
            o.y = fmaf(P.y, v4.y, fmaf(P.x, u4.y, P.z));
            o.z = fmaf(P.y, v4.z, fmaf(P.x, u4.z, P.z));
            o.w = fmaf(P.y, v4.w, fmaf(P.x, u4.w, P.z));
            *(float4*)(orow + (size_t)r * D) = o;
        }
    }

    // bmix (row-tile 0 only): bmix[b,:] = bp0*bv0 + bp1*bv1
    if (blockIdx.x == 0) {
        float bp0 = bp[2 * b], bp1 = bp[2 * b + 1];
        float4 b0 = ((const float4*)(g_bv + (size_t)(2 * b) * D))[t];
        float4 b1 = ((const float4*)(g_bv + (size_t)(2 * b + 1) * D))[t];
        float4 o;
        o.x = bp0 * b0.x + bp1 * b1.x;
        o.y = bp0 * b0.y + bp1 * b1.y;
        o.z = bp0 * b0.z + bp1 * b1.z;
        o.w = bp0 * b0.w + bp1 * b1.w;
        ((float4*)(outp + (size_t)BATCH * D * D + (size_t)b * D))[t] = o;
    }
}

// ---------------- launch ----------------
extern "C" void kernel_launch(void* const* d_in, const int* in_sizes, int n_in,
                              void* d_out, int out_size) {
    const float* x    = (const float*)d_in[0];
    const float* wp   = (const float*)d_in[1];
    const float* bpr  = (const float*)d_in[2];
    const float* iw   = (const float*)d_in[3];
    const float* ow   = (const float*)d_in[4];
    const float* dw   = (const float*)d_in[5];
    const float* bb   = (const float*)d_in[6];
    const int*   widx = (const int*)d_in[7];
    const int*   bidx = (const int*)d_in[8];
    float* outp = (float*)d_out;

    sort_kernel<<<1, NPAIR>>>(widx, bidx);
    gemm_kernel<<<dim3(4, MAXCH, 4), 128>>>(x, iw, ow, dw, bb);
    mix_ln_kernel<<<dim3(4, BATCH), 128>>>(wp, bpr, outp);
}

// round 3
// speedup vs baseline: 1.3999x; 1.0713x over previous
#include <cuda_runtime.h>
#include <cstdint>

#define D      512
#define BATCH  256
#define TOPK   2
#define NEXP   16
#define NPAIR  (BATCH * TOPK)
#define MAXCH  48          // worst-case sum ceil(M_e/16) over 16 experts = 48
#define XS_STRIDE 20       // 16 data + 4 pad floats; 80B => 16B-aligned rows

// ---------------- scratch ----------------
__device__ float g_iv[NPAIR * D];
__device__ float g_ov[NPAIR * D];
__device__ float g_dv[NPAIR * D];
__device__ float g_bv[NPAIR * D];
__device__ int   g_list_w[NPAIR];
__device__ int   g_list_b[NPAIR];
__device__ int   g_chunks_w[MAXCH];   // packed: start | e<<16 | rows<<24
__device__ int   g_chunks_b[MAXCH];
__device__ int   g_nch_w, g_nch_b;

// ---------------- kernel 0: counting sort + chunk work-list ----------------
__global__ void sort_kernel(const int* __restrict__ widx, const int* __restrict__ bidx) {
    __shared__ int cw[NEXP], cb[NEXP], offw[NEXP + 1], offb[NEXP + 1], pw[NEXP], pb[NEXP];
    int t = threadIdx.x;                       // 512 threads == pair id
    if (t < NEXP) { cw[t] = 0; cb[t] = 0; }
    __syncthreads();
    int ew = widx[t];
    int eb = bidx[t];
    atomicAdd(&cw[ew], 1);
    atomicAdd(&cb[eb], 1);
    __syncthreads();
    if (t == 0) {
        int s = 0;
        for (int e = 0; e < NEXP; e++) { offw[e] = s; s += cw[e]; }
        offw[NEXP] = s;
        int n = 0;
        for (int e = 0; e < NEXP; e++)
            for (int c = offw[e]; c < offw[e + 1]; c += 16) {
                int rows = min(16, offw[e + 1] - c);
                g_chunks_w[n++] = c | (e << 16) | (rows << 24);
            }
        g_nch_w = n;
    }
    if (t == 32) {
        int s = 0;
        for (int e = 0; e < NEXP; e++) { offb[e] = s; s += cb[e]; }
        offb[NEXP] = s;
        int n = 0;
        for (int e = 0; e < NEXP; e++)
            for (int c = offb[e]; c < offb[e + 1]; c += 16) {
                int rows = min(16, offb[e + 1] - c);
                g_chunks_b[n++] = c | (e << 16) | (rows << 24);
            }
        g_nch_b = n;
    }
    __syncthreads();
    if (t < NEXP) { pw[t] = offw[t]; pb[t] = offb[t]; }
    __syncthreads();
    int posw = atomicAdd(&pw[ew], 1);
    g_list_w[posw] = t;
    int posb = atomicAdd(&pb[eb], 1);
    g_list_b[posb] = t;
}

// ---------------- packed f32x2 helpers ----------------
__device__ __forceinline__ uint64_t dupf2(float w) {
    uint64_t r;
    asm("mov.b64 %0, {%1, %1};" : "=l"(r) : "r"(__float_as_uint(w)));
    return r;
}
__device__ __forceinline__ void fma2(uint64_t& acc, uint64_t a, uint64_t b) {
    asm("fma.rn.f32x2 %0, %1, %2, %0;" : "+l"(acc) : "l"(a), "l"(b));
}

// ---------------- kernel 1: balanced grouped GEMM (FFMA2) ----------------
// grid = (4 col-tiles of 128, MAXCH chunks, 4 banks), block = 128 threads.
// Thread owns 1 column, 16 row-accumulators held as 8 packed f32x2 regs.
// Per kk: 1 LDG (W) + 4 LDS.128 (as u64 pairs, broadcast) + 1 pack + 8 FFMA2.
__global__ __launch_bounds__(128) void gemm_kernel(
    const float* __restrict__ x,
    const float* __restrict__ iw, const float* __restrict__ ow,
    const float* __restrict__ dw, const float* __restrict__ bb) {

    int bank = blockIdx.z;
    bool isW = bank < 3;
    int nch = isW ? g_nch_w : g_nch_b;
    if ((int)blockIdx.y >= nch) return;

    __shared__ __align__(16) float xs[D * XS_STRIDE];   // 40KB

    int packed = (isW ? g_chunks_w : g_chunks_b)[blockIdx.y];
    int s    = packed & 0xFFFF;
    int e    = (packed >> 16) & 0xFF;
    int rows = (packed >> 24) & 0xFF;

    const int* list = isW ? g_list_w : g_list_b;
    const float* W  = ((bank == 0) ? iw : (bank == 1) ? ow : (bank == 2) ? dw : bb)
                      + (size_t)e * D * D;
    float* out = (bank == 0) ? g_iv : (bank == 1) ? g_ov : (bank == 2) ? g_dv : g_bv;

    int t   = threadIdx.x;
    int col = blockIdx.x * 128 + t;

    // fill transposed x chunk (coalesced LDG; zero-pad rows >= rows)
    for (int idx = t; idx < 16 * D; idx += 128) {
        int m  = idx >> 9;
        int kk = idx & (D - 1);
        float val = 0.0f;
        if (m < rows) val = x[(list[s + m] >> 1) * D + kk];
        xs[kk * XS_STRIDE + m] = val;
    }
    __syncthreads();

    uint64_t acc[8];
#pragma unroll
    for (int j = 0; j < 8; j++) acc[j] = 0ull;

    const float* Wc = W + col;
#pragma unroll 8
    for (int kk = 0; kk < D; kk++) {
        float w = Wc[kk * D];
        uint64_t ww = dupf2(w);
        const ulonglong2* row = (const ulonglong2*)&xs[kk * XS_STRIDE];
        ulonglong2 r0 = row[0];
        ulonglong2 r1 = row[1];
        ulonglong2 r2 = row[2];
        ulonglong2 r3 = row[3];
        fma2(acc[0], r0.x, ww);
        fma2(acc[1], r0.y, ww);
        fma2(acc[2], r1.x, ww);
        fma2(acc[3], r1.y, ww);
        fma2(acc[4], r2.x, ww);
        fma2(acc[5], r2.y, ww);
        fma2(acc[6], r3.x, ww);
        fma2(acc[7], r3.y, ww);
    }

#pragma unroll
    for (int j = 0; j < 8; j++) {
        float2 f2 = *reinterpret_cast<float2*>(&acc[j]);
        int r = 2 * j;
        if (r < rows)     out[(size_t)list[s + r] * D + col]     = f2.x;
        if (r + 1 < rows) out[(size_t)list[s + r + 1] * D + col] = f2.y;
    }
}

// ---------------- kernel 2: rank-2 mix + analytic LayerNorm + bmix ----------------
// Wmix[b,i,o] = p_i*u_o + q_i*v_o + delta_{io}*g_i. Row mean/var closed-form from
// Su,Sv,Suu,Svv,Suv. Per-row params folded to (pr,qr,c,gr) = (p*rstd, q*rstd,
// -mean*rstd, g*rstd) so inner body = 1 LDS.128 + 8 FFMA + STG.128.
__global__ __launch_bounds__(128) void mix_ln_kernel(
    const float* __restrict__ wp, const float* __restrict__ bp,
    float* __restrict__ outp) {

    int b  = blockIdx.y;
    int r0 = blockIdx.x * 128;
    int t  = threadIdx.x;

    __shared__ float u[D], v[D];
    __shared__ __align__(16) float4 sparams[128];   // {pr, qr, c, gr}
    __shared__ float red[4][5];

    const float* u_g = g_ov + (size_t)(2 * b) * D;
    const float* v_g = g_ov + (size_t)(2 * b + 1) * D;
    float4 u4 = ((const float4*)u_g)[t];
    float4 v4 = ((const float4*)v_g)[t];
    ((float4*)u)[t] = u4;
    ((float4*)v)[t] = v4;

    float lu  = u4.x + u4.y + u4.z + u4.w;
    float lv  = v4.x + v4.y + v4.z + v4.w;
    float luu = u4.x * u4.x + u4.y * u4.y + u4.z * u4.z + u4.w * u4.w;
    float lvv = v4.x * v4.x + v4.y * v4.y + v4.z * v4.z + v4.w * v4.w;
    float luv = u4.x * v4.x + u4.y * v4.y + u4.z * v4.z + u4.w * v4.w;
#pragma unroll
    for (int sft = 16; sft > 0; sft >>= 1) {
        lu  += __shfl_xor_sync(0xffffffffu, lu, sft);
        lv  += __shfl_xor_sync(0xffffffffu, lv, sft);
        luu += __shfl_xor_sync(0xffffffffu, luu, sft);
        lvv += __shfl_xor_sync(0xffffffffu, lvv, sft);
        luv += __shfl_xor_sync(0xffffffffu, luv, sft);
    }
    int lane = t & 31, wrp = t >> 5;
    if (lane == 0) {
        red[wrp][0] = lu; red[wrp][1] = lv; red[wrp][2] = luu;
        red[wrp][3] = lvv; red[wrp][4] = luv;
    }
    __syncthreads();
    float Su  = red[0][0] + red[1][0] + red[2][0] + red[3][0];
    float Sv  = red[0][1] + red[1][1] + red[2][1] + red[3][1];
    float Suu = red[0][2] + red[1][2] + red[2][2] + red[3][2];
    float Svv = red[0][3] + red[1][3] + red[2][3] + red[3][3];
    float Suv = red[0][4] + red[1][4] + red[2][4] + red[3][4];

    {
        int i = r0 + t;
        float wp0 = wp[2 * b], wp1 = wp[2 * b + 1];
        float p = wp0 * g_iv[(size_t)(2 * b) * D + i];
        float q = wp1 * g_iv[(size_t)(2 * b + 1) * D + i];
        float g = wp0 * g_dv[(size_t)(2 * b) * D + i]
                + wp1 * g_dv[(size_t)(2 * b + 1) * D + i];
        const float invD = 1.0f / (float)D;
        float mean = (p * Su + q * Sv + g) * invD;
        float ex2  = (p * p * Suu + 2.0f * p * q * Suv + q * q * Svv
                      + 2.0f * g * (p * u[i] + q * v[i]) + g * g) * invD;
        float var  = ex2 - mean * mean;
        float rstd = rsqrtf(var + 1e-5f);
        float4 pr;
        pr.x = p * rstd;
        pr.y = q * rstd;
        pr.z = -mean * rstd;
        pr.w = g * rstd;
        sparams[t] = pr;
    }
    __syncthreads();

    float* orow = outp + ((size_t)b * D + r0) * D + (t << 2);

    if (wrp == blockIdx.x) {
        // this warp owns the diagonal columns of this row tile
        int base = t << 2;
#pragma unroll 4
        for (int r = 0; r < 128; r++) {
            float4 P = sparams[r];
            float4 o;
            o.x = fmaf(P.y, v4.x, fmaf(P.x, u4.x, P.z));
            o.y = fmaf(P.y, v4.y, fmaf(P.x, u4.y, P.z));
            o.z = fmaf(P.y, v4.z, fmaf(P.x, u4.z, P.z));
            o.w = fmaf(P.y, v4.w, fmaf(P.x, u4.w, P.z));
            int dj = (r0 + r) - base;
            if (dj == 0) o.x += P.w;
            if (dj == 1) o.y += P.w;
            if (dj == 2) o.z += P.w;
            if (dj == 3) o.w += P.w;
            *(float4*)(orow + (size_t)r * D) = o;
        }
    } else {
        // diag never lands in these columns: clean streaming loop
#pragma unroll 4
        for (int r = 0; r < 128; r++) {
            float4 P = sparams[r];
            float4 o;
            o.x = fmaf(P.y, v4.x, fmaf(P.x, u4.x, P.z));
            o.y = fmaf(P.y, v4.y, fmaf(P.x, u4.y, P.z));
            o.z = fmaf(P.y, v4.z, fmaf(P.x, u4.z, P.z));
            o.w = fmaf(P.y, v4.w, fmaf(P.x, u4.w, P.z));
            *(float4*)(orow + (size_t)r * D) = o;
        }
    }

    // bmix (row-tile 0 only): bmix[b,:] = bp0*bv0 + bp1*bv1
    if (blockIdx.x == 0) {
        float bp0 = bp[2 * b], bp1 = bp[2 * b + 1];
        float4 b0 = ((const float4*)(g_bv + (size_t)(2 * b) * D))[t];
        float4 b1 = ((const float4*)(g_bv + (size_t)(2 * b + 1) * D))[t];
        float4 o;
        o.x = bp0 * b0.x + bp1 * b1.x;
        o.y = bp0 * b0.y + bp1 * b1.y;
        o.z = bp0 * b0.z + bp1 * b1.z;
        o.w = bp0 * b0.w + bp1 * b1.w;
        ((float4*)(outp + (size_t)BATCH * D * D + (size_t)b * D))[t] = o;
    }
}

// ---------------- launch ----------------
extern "C" void kernel_launch(void* const* d_in, const int* in_sizes, int n_in,
                              void* d_out, int out_size) {
    const float* x    = (const float*)d_in[0];
    const float* wp   = (const float*)d_in[1];
    const float* bpr  = (const float*)d_in[2];
    const float* iw   = (const float*)d_in[3];
    const float* ow   = (const float*)d_in[4];
    const float* dw   = (const float*)d_in[5];
    const float* bb   = (const float*)d_in[6];
    const int*   widx = (const int*)d_in[7];
    const int*   bidx = (const int*)d_in[8];
    float* outp = (float*)d_out;

    sort_kernel<<<1, NPAIR>>>(widx, bidx);
    gemm_kernel<<<dim3(4, MAXCH, 4), 128>>>(x, iw, ow, dw, bb);
    mix_ln_kernel<<<dim3(4, BATCH), 128>>>(wp, bpr, outp);
}